// round 1
// baseline (speedup 1.0000x reference)
#include <cuda_runtime.h>
#include <math.h>

// Problem constants
#define BATCH 16
#define LROWS 192   // 6*L rows of raw
#define AC    2046  // attributor columns
#define MC    2048  // M = A + 2
#define LD    32    // L (W_2 output dim)
#define TM    128   // columns of m per block in main kernel

// Scratch (device globals; no allocation allowed)
__device__ float g_wq[BATCH][2][64];   // wq[b][n][j] = sum_l W2[j,l] * Key[b,l,col_n]
__device__ float g_wk[BATCH][2][64];   // wk[b][n][j] = sum_l W2[64+j,l] * Query[b,l,col_n]
__device__ float g_S[BATCH][2][64];    // S[b][n][j]  = sum_m reluV[j,m] * causal[b,m,col_n]
__device__ float g_A[2][MC];           // adj[m][col_n]
__device__ float g_P[2][MC];           // adj[m][col_n] * iw[m][col_n]
__device__ float g_R[2][MC];           // adj[col_n][m] * iw[col_n][m]

// ---------------------------------------------------------------------------
// Kernel A: per (batch b, special col n in {0 -> user/col0, 1 -> item/col2047})
// compute Query/Key of the special column, fold with W2 into wq/wk; zero g_S.
// grid (16,2), 128 threads.
// ---------------------------------------------------------------------------
__global__ void setup_kernel(const float* __restrict__ user,
                             const float* __restrict__ item,
                             const float* __restrict__ W2) {
    int b = blockIdx.x;
    int n = blockIdx.y;
    const float* src = (n ? item : user) + b * LROWS;
    __shared__ float xr[128];     // relu of rows 0..127 of the special column
    __shared__ float qs[32];      // Query[b, l, col_n]
    __shared__ float ks[32];      // Key[b, l, col_n]
    int t = threadIdx.x;          // 128 threads
    xr[t] = fmaxf(src[t], 0.0f);
    __syncthreads();
    if (t < 32) {
        float s = 0.0f;
        #pragma unroll
        for (int j = 0; j < 64; j++) s = fmaf(xr[j], W2[j * LD + t], s);
        qs[t] = s;
    } else if (t < 64) {
        int l = t - 32;
        float s = 0.0f;
        #pragma unroll
        for (int j = 0; j < 64; j++) s = fmaf(xr[64 + j], W2[(64 + j) * LD + l], s);
        ks[l] = s;
    }
    __syncthreads();
    if (t < 64) {
        float swq = 0.0f, swk = 0.0f;
        #pragma unroll
        for (int l = 0; l < 32; l++) {
            swq = fmaf(W2[t * LD + l],        ks[l], swq);
            swk = fmaf(W2[(64 + t) * LD + l], qs[l], swk);
        }
        g_wq[b][n][t] = swq;
        g_wk[b][n][t] = swk;
        g_S[b][n][t] = 0.0f;      // zero the accumulator every launch
    }
}

// ---------------------------------------------------------------------------
// Kernel B0: pack the needed rows/cols of adj and initial_weight.
// ---------------------------------------------------------------------------
__global__ void pack_kernel(const float* __restrict__ adj,
                            const float* __restrict__ iw) {
    int m = blockIdx.x * blockDim.x + threadIdx.x;
    if (m >= MC) return;
    size_t row = (size_t)m * MC;
    float a0 = adj[row];
    float a1 = adj[row + (MC - 1)];
    g_A[0][m] = a0;
    g_A[1][m] = a1;
    g_P[0][m] = a0 * iw[row];
    g_P[1][m] = a1 * iw[row + (MC - 1)];
    g_R[0][m] = adj[m] * iw[m];
    size_t lastrow = (size_t)(MC - 1) * MC + m;
    g_R[1][m] = adj[lastrow] * iw[lastrow];
}

// ---------------------------------------------------------------------------
// Kernel B: main streaming kernel. grid (mb=16, b=16), 384 threads.
//   group 0 (t 0..127):    Q-row dots  -> hq_sh
//   group 1 (t 128..255):  K-row dots  -> hk_sh
//   group 2 (t 256..383):  V-row relus -> Vsh
// then sigmoid-causal per (n, m), then (j,n) x m reduction into g_S.
// ---------------------------------------------------------------------------
__global__ __launch_bounds__(384) void main_kernel(
    const float* __restrict__ user, const float* __restrict__ item,
    const float* __restrict__ attributor, const float* __restrict__ W1) {

    __shared__ float Vsh[64][TM + 1];   // padded: bank-conflict-free row reads
    __shared__ float hq_sh[2][TM];
    __shared__ float hk_sh[2][TM];
    __shared__ float c_sh[2][TM];
    __shared__ float wq_sh[2][64];
    __shared__ float wk_sh[2][64];

    int b  = blockIdx.y;
    int mb = blockIdx.x;
    int t  = threadIdx.x;
    int group = t >> 7;          // 0,1,2
    int ml = t & (TM - 1);
    int m  = mb * TM + ml;

    if (t < 128) {
        ((float*)wq_sh)[t] = ((const float*)g_wq[b])[t];
        ((float*)wk_sh)[t] = ((const float*)g_wk[b])[t];
    }
    __syncthreads();

    bool isU = (m == 0), isI = (m == MC - 1);
    bool special = isU || isI;
    int mm1 = special ? 0 : (m - 1);    // safe offset (never deref OOB)
    const float* ap = attributor + ((size_t)b * LROWS + group * 64) * AC + mm1;
    const float* wp = W1 + (size_t)(group * 64) * AC + mm1;
    const float* up = (isU ? user : item) + b * LROWS + group * 64;

    if (group == 0) {
        float h0 = 0.0f, h1 = 0.0f;
        #pragma unroll 8
        for (int j = 0; j < 64; j++) {
            float x = special ? up[j] : ap[(size_t)j * AC] * wp[(size_t)j * AC];
            x = fmaxf(x, 0.0f);
            h0 = fmaf(x, wq_sh[0][j], h0);
            h1 = fmaf(x, wq_sh[1][j], h1);
        }
        hq_sh[0][ml] = h0;
        hq_sh[1][ml] = h1;
    } else if (group == 1) {
        float h0 = 0.0f, h1 = 0.0f;
        #pragma unroll 8
        for (int j = 0; j < 64; j++) {
            float x = special ? up[j] : ap[(size_t)j * AC] * wp[(size_t)j * AC];
            x = fmaxf(x, 0.0f);
            h0 = fmaf(x, wk_sh[0][j], h0);
            h1 = fmaf(x, wk_sh[1][j], h1);
        }
        hk_sh[0][ml] = h0;
        hk_sh[1][ml] = h1;
    } else {
        #pragma unroll 8
        for (int j = 0; j < 64; j++) {
            float x = special ? up[j] : ap[(size_t)j * AC] * wp[(size_t)j * AC];
            Vsh[j][ml] = fmaxf(x, 0.0f);
        }
    }
    __syncthreads();

    // causal[b, m, col_n] = sigmoid(h[m,n] - h[n,m]) * adj[m, col_n]
    if (t < 256) {
        int n  = t >> 7;
        int mm = t & (TM - 1);
        int mg = mb * TM + mm;
        float d = hq_sh[n][mm] * g_P[n][mg] - hk_sh[n][mm] * g_R[n][mg];
        c_sh[n][mm] = g_A[n][mg] / (1.0f + expf(-d));
    }
    __syncthreads();

    // S[b][n][j] += sum_mm Vsh[j][mm] * c_sh[n][mm]
    if (t < 128) {
        int n = t >> 6;
        int j = t & 63;
        float s = 0.0f;
        #pragma unroll 8
        for (int mm = 0; mm < TM; mm++)
            s = fmaf(Vsh[j][mm], c_sh[n][mm], s);
        atomicAdd(&g_S[b][n][j], s);
    }
}

// ---------------------------------------------------------------------------
// Kernel C: final Value projection. out[b, l, n] = sum_j W2[128+j, l] * S[b][n][j]
// Output layout (B, L, 2) row-major: index = b*64 + l*2 + n  == t.
// ---------------------------------------------------------------------------
__global__ void final_kernel(const float* __restrict__ W2, float* __restrict__ out) {
    int t = threadIdx.x;          // 1024 threads
    int b = t >> 6;
    int l = (t >> 1) & 31;
    int n = t & 1;
    float s = 0.0f;
    #pragma unroll
    for (int j = 0; j < 64; j++)
        s = fmaf(W2[(128 + j) * LD + l], g_S[b][n][j], s);
    out[t] = s;
}

extern "C" void kernel_launch(void* const* d_in, const int* in_sizes, int n_in,
                              void* d_out, int out_size) {
    const float* user       = (const float*)d_in[0];
    const float* item       = (const float*)d_in[1];
    const float* attributor = (const float*)d_in[2];
    const float* adj        = (const float*)d_in[3];
    const float* iw         = (const float*)d_in[4];
    const float* W1         = (const float*)d_in[5];
    const float* W2         = (const float*)d_in[6];
    float* out = (float*)d_out;

    setup_kernel<<<dim3(BATCH, 2), 128>>>(user, item, W2);
    pack_kernel<<<2, 1024>>>(adj, iw);
    main_kernel<<<dim3(MC / TM, BATCH), 384>>>(user, item, attributor, W1);
    final_kernel<<<1, 1024>>>(W2, out);
}